// round 8
// baseline (speedup 1.0000x reference)
#include <cuda_runtime.h>
#include <cstdint>
#include <math.h>

#define Ee 768
#define Hh 12
#define Dd 64
#define Bb 8
#define Nn 1024
#define Mtot (Bb * Nn)   // 8192

// Scratch (static device globals; allocation is forbidden)
__device__ float g_q[(size_t)Mtot * Ee];
__device__ float g_k[(size_t)Mtot * Ee];
__device__ float g_v[(size_t)Mtot * Ee];
__device__ float g_attn[(size_t)Mtot * Ee];

// ======================= helpers ===========================================
__device__ __forceinline__ uint32_t f2tf32(float f) {
    uint32_t r;
    asm("cvt.rna.tf32.f32 %0, %1;" : "=r"(r) : "f"(f));
    return r;
}
__device__ __forceinline__ float f2tf32f(float f) {
    return __uint_as_float(f2tf32(f));
}
__device__ __forceinline__ uint32_t smem_u32(const void* p) {
    uint32_t a;
    asm("{ .reg .u64 t; cvta.to.shared.u64 t, %1; cvt.u32.u64 %0, t; }" : "=r"(a) : "l"(p));
    return a;
}
__device__ __forceinline__ void cp16(uint32_t dst, const void* src) {
    asm volatile("cp.async.cg.shared.global [%0], [%1], 16;" :: "r"(dst), "l"(src));
}

__device__ __forceinline__ void mma_tf32(float* d, const uint32_t* a, const uint32_t* b) {
    asm volatile(
        "mma.sync.aligned.m16n8k8.row.col.f32.tf32.tf32.f32 "
        "{%0,%1,%2,%3}, {%4,%5,%6,%7}, {%8,%9}, {%0,%1,%2,%3};"
        : "+f"(d[0]), "+f"(d[1]), "+f"(d[2]), "+f"(d[3])
        : "r"(a[0]), "r"(a[1]), "r"(a[2]), "r"(a[3]), "r"(b[0]), "r"(b[1]));
}

// ======================= tf32 tensor-core GEMM, 4-stage cp.async ==========
// C[M,Nc] = (A[M,K] @ W[Nc,K]^T + bias) * scale   (torch-style weights)
// CTA 128x128, BK=16, 256 threads (8 warps, 2(m) x 4(n), warp = 64x32).
// fp32 staged raw via cp.async; rna->tf32 rounding done at fragment load.
#define BM 128
#define BN 128
#define BKt 16
#define PITCH 20
#define GSTAGES 4
#define GEMM_SMEM (GSTAGES * BM * PITCH * 4 * 2)   // 81920 bytes

__global__ __launch_bounds__(256)
void gemm_mma(const float* __restrict__ A, const float* __restrict__ W,
              const float* __restrict__ bias, float* __restrict__ C,
              int M, int Nc, int K, float scale)
{
    extern __shared__ float gsm[];
    float* AsB = gsm;                              // [4][128][20]
    float* BsB = gsm + GSTAGES * BM * PITCH;       // [4][128][20]
    const uint32_t smA = smem_u32(AsB);
    const uint32_t smB = smem_u32(BsB);

    const int tid  = threadIdx.x;
    const int lane = tid & 31;
    const int w    = tid >> 5;
    const int wr   = w & 1;
    const int wc   = w >> 1;
    const int rowBase = blockIdx.y * BM;
    const int colBase = blockIdx.x * BN;

    float acc[4][4][4];
    #pragma unroll
    for (int i = 0; i < 4; i++)
        #pragma unroll
        for (int j = 0; j < 4; j++)
            #pragma unroll
            for (int q = 0; q < 4; q++) acc[i][j][q] = 0.f;

    // Loader: each thread copies 2 float4 of A and 2 float4 of B per chunk
    const int lrow = tid >> 1;             // 0..127
    const int lcq  = (tid & 1) * 8;        // 0 or 8
    const float* Ag = A + (size_t)(rowBase + lrow) * K + lcq;
    const float* Wg = W + (size_t)(colBase + lrow) * K + lcq;
    const uint32_t soff = (uint32_t)(lrow * PITCH + lcq) * 4;

    const int NSTEP = K / BKt;   // 48

    // Prologue: chunks 0..2 into stages 0..2
    #pragma unroll
    for (int s = 0; s < 3; s++) {
        uint32_t dA = smA + s * (BM * PITCH * 4) + soff;
        uint32_t dB = smB + s * (BM * PITCH * 4) + soff;
        const float* a = Ag + s * BKt;
        const float* b = Wg + s * BKt;
        cp16(dA, a); cp16(dA + 16, a + 4);
        cp16(dB, b); cp16(dB + 16, b + 4);
        asm volatile("cp.async.commit_group;" ::: "memory");
    }

    const int mrow = wr * 64 + (lane >> 2);
    const int ncol = wc * 32 + (lane >> 2);
    const int klo  = lane & 3;

    for (int c = 0; c < NSTEP; c++) {
        asm volatile("cp.async.wait_group 2;" ::: "memory");
        __syncthreads();

        // issue chunk c+3 into stage (c+3)%4  (stage freed at iter c-1)
        if (c + 3 < NSTEP) {
            int s = (c + 3) & 3;
            uint32_t dA = smA + s * (BM * PITCH * 4) + soff;
            uint32_t dB = smB + s * (BM * PITCH * 4) + soff;
            const float* a = Ag + (c + 3) * BKt;
            const float* b = Wg + (c + 3) * BKt;
            cp16(dA, a); cp16(dA + 16, a + 4);
            cp16(dB, b); cp16(dB + 16, b + 4);
        }
        asm volatile("cp.async.commit_group;" ::: "memory");

        const float* Asc = AsB + (c & 3) * (BM * PITCH);
        const float* Bsc = BsB + (c & 3) * (BM * PITCH);

        #pragma unroll
        for (int ks = 0; ks < BKt; ks += 8) {
            uint32_t af[4][4], bf[4][2];
            #pragma unroll
            for (int mf = 0; mf < 4; mf++) {
                af[mf][0] = f2tf32(Asc[(mrow + mf * 16    ) * PITCH + ks + klo]);
                af[mf][1] = f2tf32(Asc[(mrow + mf * 16 + 8) * PITCH + ks + klo]);
                af[mf][2] = f2tf32(Asc[(mrow + mf * 16    ) * PITCH + ks + klo + 4]);
                af[mf][3] = f2tf32(Asc[(mrow + mf * 16 + 8) * PITCH + ks + klo + 4]);
            }
            #pragma unroll
            for (int nf = 0; nf < 4; nf++) {
                bf[nf][0] = f2tf32(Bsc[(ncol + nf * 8) * PITCH + ks + klo]);
                bf[nf][1] = f2tf32(Bsc[(ncol + nf * 8) * PITCH + ks + klo + 4]);
            }
            #pragma unroll
            for (int mf = 0; mf < 4; mf++)
                #pragma unroll
                for (int nf = 0; nf < 4; nf++)
                    mma_tf32(acc[mf][nf], af[mf], bf[nf]);
        }
    }

    #pragma unroll
    for (int mf = 0; mf < 4; mf++) {
        int r0 = rowBase + wr * 64 + mf * 16 + (lane >> 2);
        #pragma unroll
        for (int nf = 0; nf < 4; nf++) {
            int c0 = colBase + wc * 32 + nf * 8 + (lane & 3) * 2;
            float b0 = bias[c0], b1 = bias[c0 + 1];
            float2 lo, hi;
            lo.x = (acc[mf][nf][0] + b0) * scale;
            lo.y = (acc[mf][nf][1] + b1) * scale;
            hi.x = (acc[mf][nf][2] + b0) * scale;
            hi.y = (acc[mf][nf][3] + b1) * scale;
            *(float2*)&C[(size_t)r0 * Nc + c0]       = lo;
            *(float2*)&C[(size_t)(r0 + 8) * Nc + c0] = hi;
        }
    }
}

// ---------------------------------------------------------------------------
// Flash attention via mma.sync tf32, with next-tile bias prefetched into the
// (freed) S accumulators during the PV phase.
// CTA: 128 q-rows x (h,b); k-tile 64; 8 warps as 4(m) x 2(n); warp tile 32x32.
// ---------------------------------------------------------------------------
#define QP 68
#define VPIT 72
#define QS_OFF 0
#define KP_OFF2 (128 * QP)            // 8704
#define VS_OFF2 (KP_OFF2 + 128 * QP)  // 17408
#define ST_OFF  (VS_OFF2 + 64 * VPIT) // 22016
#define ATTN_SMEM ((ST_OFF + 512) * 4)  // 90112 bytes

__global__ __launch_bounds__(256, 2)
void attn_mma(const float* __restrict__ abias)
{
    extern __shared__ float sm[];
    float* Qs = sm + QS_OFF;
    float* KP = sm + KP_OFF2;
    float* Vs = sm + VS_OFF2;
    float* stMax = sm + ST_OFF;        // [128][2]
    float* stSum = sm + ST_OFF + 256;  // [128][2]

    const int tid  = threadIdx.x;
    const int lane = tid & 31;
    const int w    = tid >> 5;
    const int ms   = (w & 3) * 32;
    const int nsi  = w >> 2;
    const int ns   = nsi * 32;
    const int lr   = lane >> 2;
    const int lc   = lane & 3;

    const int q0 = blockIdx.x * 128;
    const int h  = blockIdx.y;
    const int b  = blockIdx.z;

    const float* qg = g_q + ((size_t)b * Nn + q0) * Ee + h * Dd;
    const float* kg = g_k + (size_t)b * Nn * Ee + h * Dd;
    const float* vg = g_v + (size_t)b * Nn * Ee + h * Dd;
    const float* bg = abias + (((size_t)b * Hh + h) * Nn + q0) * Nn;

    // Load Q once (tf32-rounded), row-major [q][d]
    #pragma unroll
    for (int it = 0; it < 8; it++) {
        int idx = tid + it * 256;
        int r = idx >> 4;
        int c4 = (idx & 15) * 4;
        float4 v = *(const float4*)&qg[(size_t)r * Ee + c4];
        float4 t;
        t.x = f2tf32f(v.x); t.y = f2tf32f(v.y); t.z = f2tf32f(v.z); t.w = f2tf32f(v.w);
        *(float4*)&Qs[r * QP + c4] = t;
    }

    float o[2][4][4];
    float m_i[4], l_i[4];
    #pragma unroll
    for (int r4 = 0; r4 < 4; r4++) { m_i[r4] = -1e30f; l_i[r4] = 0.f; }
    #pragma unroll
    for (int mf = 0; mf < 2; mf++)
        #pragma unroll
        for (int nf = 0; nf < 4; nf++)
            #pragma unroll
            for (int e = 0; e < 4; e++) o[mf][nf][e] = 0.f;

    // Preload bias for tile 0 into the S accumulators (C-frag layout)
    float c[2][4][4];
    #pragma unroll
    for (int mf = 0; mf < 2; mf++)
        #pragma unroll
        for (int nf = 0; nf < 4; nf++) {
            const float* bp = bg + (size_t)(ms + 16 * mf + lr) * Nn + ns + 8 * nf + 2 * lc;
            float2 t0 = *(const float2*)bp;
            float2 t1 = *(const float2*)(bp + 8 * Nn);
            c[mf][nf][0] = t0.x; c[mf][nf][1] = t0.y;
            c[mf][nf][2] = t1.x; c[mf][nf][3] = t1.y;
        }

    for (int kt = 0; kt < Nn / 64; kt++) {
        const int k0 = kt * 64;
        __syncthreads();   // prior iter's P/V reads done (and Q fill on iter 0)

        // K tile -> KP, V tile -> Vs (tf32-rounded)
        #pragma unroll
        for (int it = 0; it < 4; it++) {
            int idx = tid + it * 256;
            int r = idx >> 4;
            int c4 = (idx & 15) * 4;
            float4 kv = *(const float4*)&kg[(size_t)(k0 + r) * Ee + c4];
            float4 tk;
            tk.x = f2tf32f(kv.x); tk.y = f2tf32f(kv.y); tk.z = f2tf32f(kv.z); tk.w = f2tf32f(kv.w);
            *(float4*)&KP[r * QP + c4] = tk;
            float4 vv = *(const float4*)&vg[(size_t)(k0 + r) * Ee + c4];
            float4 tv;
            tv.x = f2tf32f(vv.x); tv.y = f2tf32f(vv.y); tv.z = f2tf32f(vv.z); tv.w = f2tf32f(vv.w);
            *(float4*)&Vs[r * VPIT + c4] = tv;
        }
        __syncthreads();

        // S = Q K^T  (bias already sits in c)
        #pragma unroll
        for (int ks = 0; ks < 8; ks++) {
            int d0 = ks * 8;
            uint32_t af[2][4], bf[4][2];
            #pragma unroll
            for (int mf = 0; mf < 2; mf++) {
                const float* qp = Qs + (ms + 16 * mf + lr) * QP + d0 + lc;
                af[mf][0] = __float_as_uint(qp[0]);
                af[mf][1] = __float_as_uint(qp[8 * QP]);
                af[mf][2] = __float_as_uint(qp[4]);
                af[mf][3] = __float_as_uint(qp[8 * QP + 4]);
            }
            #pragma unroll
            for (int nf = 0; nf < 4; nf++) {
                const float* kp = KP + (ns + 8 * nf + lr) * QP + d0 + lc;
                bf[nf][0] = __float_as_uint(kp[0]);
                bf[nf][1] = __float_as_uint(kp[4]);
            }
            #pragma unroll
            for (int mf = 0; mf < 2; mf++)
                #pragma unroll
                for (int nf = 0; nf < 4; nf++)
                    mma_tf32(c[mf][nf], af[mf], bf[nf]);
        }

        // Partial row max over this warp's 32 cols
        float pm[4];
        #pragma unroll
        for (int r4 = 0; r4 < 4; r4++) {
            int mf = r4 >> 1, hf = r4 & 1;
            float mx = fmaxf(c[mf][0][2 * hf], c[mf][0][2 * hf + 1]);
            #pragma unroll
            for (int nf = 1; nf < 4; nf++)
                mx = fmaxf(mx, fmaxf(c[mf][nf][2 * hf], c[mf][nf][2 * hf + 1]));
            mx = fmaxf(mx, __shfl_xor_sync(0xffffffffu, mx, 1));
            mx = fmaxf(mx, __shfl_xor_sync(0xffffffffu, mx, 2));
            pm[r4] = mx;
        }
        if (lc == 0) {
            #pragma unroll
            for (int r4 = 0; r4 < 4; r4++)
                stMax[(ms + lr + 8 * r4) * 2 + nsi] = pm[r4];
        }
        __syncthreads();   // stats visible; all warps done with K reads

        float alpha[4], psum[4];
        #pragma unroll
        for (int r4 = 0; r4 < 4; r4++) {
            float mo = stMax[(ms + lr + 8 * r4) * 2 + (1 - nsi)];
            float mt = fmaxf(pm[r4], mo);
            float mnew = fmaxf(m_i[r4], mt);
            alpha[r4] = __expf(m_i[r4] - mnew);
            m_i[r4] = mnew;
            psum[r4] = 0.f;
        }

        // exp, partial sums, store P (tf32-rounded) into KP
        #pragma unroll
        for (int mf = 0; mf < 2; mf++) {
            #pragma unroll
            for (int nf = 0; nf < 4; nf++) {
                #pragma unroll
                for (int e = 0; e < 4; e++) {
                    int r4 = mf * 2 + (e >> 1);
                    float p = __expf(c[mf][nf][e] - m_i[r4]);
                    psum[r4] += p;
                    c[mf][nf][e] = f2tf32f(p);
                }
                float* pp = KP + (ms + 16 * mf + lr) * QP + ns + 8 * nf + 2 * lc;
                *(float2*)pp = make_float2(c[mf][nf][0], c[mf][nf][1]);
                *(float2*)(pp + 8 * QP) = make_float2(c[mf][nf][2], c[mf][nf][3]);
            }
        }

        // ---- c is now free: prefetch next tile's bias into it (hidden by PV)
        {
            const int k0n = ((kt + 1) & (Nn / 64 - 1)) * 64;  // wraps harmlessly on last iter
            #pragma unroll
            for (int mf = 0; mf < 2; mf++)
                #pragma unroll
                for (int nf = 0; nf < 4; nf++) {
                    const float* bp = bg + (size_t)(ms + 16 * mf + lr) * Nn + k0n + ns + 8 * nf + 2 * lc;
                    float2 t0 = *(const float2*)bp;
                    float2 t1 = *(const float2*)(bp + 8 * Nn);
                    c[mf][nf][0] = t0.x; c[mf][nf][1] = t0.y;
                    c[mf][nf][2] = t1.x; c[mf][nf][3] = t1.y;
                }
        }

        #pragma unroll
        for (int r4 = 0; r4 < 4; r4++) {
            psum[r4] += __shfl_xor_sync(0xffffffffu, psum[r4], 1);
            psum[r4] += __shfl_xor_sync(0xffffffffu, psum[r4], 2);
        }
        if (lc == 0) {
            #pragma unroll
            for (int r4 = 0; r4 < 4; r4++)
                stSum[(ms + lr + 8 * r4) * 2 + nsi] = psum[r4];
        }
        __syncthreads();   // P fully written; sums visible

        #pragma unroll
        for (int r4 = 0; r4 < 4; r4++) {
            float so = stSum[(ms + lr + 8 * r4) * 2 + (1 - nsi)];
            l_i[r4] = l_i[r4] * alpha[r4] + psum[r4] + so;
        }
        #pragma unroll
        for (int mf = 0; mf < 2; mf++)
            #pragma unroll
            for (int nf = 0; nf < 4; nf++) {
                int r40 = mf * 2, r41 = mf * 2 + 1;
                o[mf][nf][0] *= alpha[r40];
                o[mf][nf][1] *= alpha[r40];
                o[mf][nf][2] *= alpha[r41];
                o[mf][nf][3] *= alpha[r41];
            }

        // O += P V
        #pragma unroll
        for (int ks = 0; ks < 8; ks++) {
            int kk0 = ks * 8;
            uint32_t af[2][4], bf[4][2];
            #pragma unroll
            for (int mf = 0; mf < 2; mf++) {
                const float* pp = KP + (ms + 16 * mf + lr) * QP + kk0 + lc;
                af[mf][0] = __float_as_uint(pp[0]);
                af[mf][1] = __float_as_uint(pp[8 * QP]);
                af[mf][2] = __float_as_uint(pp[4]);
                af[mf][3] = __float_as_uint(pp[8 * QP + 4]);
            }
            #pragma unroll
            for (int nf = 0; nf < 4; nf++) {
                const float* vp = Vs + (kk0 + lc) * VPIT + ns + 8 * nf + lr;
                bf[nf][0] = __float_as_uint(vp[0]);
                bf[nf][1] = __float_as_uint(vp[4 * VPIT]);
            }
            #pragma unroll
            for (int mf = 0; mf < 2; mf++)
                #pragma unroll
                for (int nf = 0; nf < 4; nf++)
                    mma_tf32(o[mf][nf], af[mf], bf[nf]);
        }
    }

    // Normalize and write back
    float* og = g_attn + ((size_t)b * Nn + q0) * Ee + h * Dd;
    #pragma unroll
    for (int mf = 0; mf < 2; mf++) {
        float inv0 = 1.f / l_i[mf * 2];
        float inv1 = 1.f / l_i[mf * 2 + 1];
        int r0 = ms + 16 * mf + lr;
        #pragma unroll
        for (int nf = 0; nf < 4; nf++) {
            int cc = ns + 8 * nf + 2 * lc;
            *(float2*)&og[(size_t)r0 * Ee + cc] =
                make_float2(o[mf][nf][0] * inv0, o[mf][nf][1] * inv0);
            *(float2*)&og[(size_t)(r0 + 8) * Ee + cc] =
                make_float2(o[mf][nf][2] * inv1, o[mf][nf][3] * inv1);
        }
    }
}

// ---------------------------------------------------------------------------
extern "C" void kernel_launch(void* const* d_in, const int* in_sizes, int n_in,
                              void* d_out, int out_size)
{
    const float* query = (const float*)d_in[0];
    const float* abias = (const float*)d_in[1];
    const float* Wq = (const float*)d_in[2];
    const float* bq = (const float*)d_in[3];
    const float* Wk = (const float*)d_in[4];
    const float* bk = (const float*)d_in[5];
    const float* Wv = (const float*)d_in[6];
    const float* bv = (const float*)d_in[7];
    const float* Wo = (const float*)d_in[8];
    const float* bo = (const float*)d_in[9];
    float* out = (float*)d_out;

    float* gq; cudaGetSymbolAddress((void**)&gq, g_q);
    float* gk; cudaGetSymbolAddress((void**)&gk, g_k);
    float* gv; cudaGetSymbolAddress((void**)&gv, g_v);
    float* ga; cudaGetSymbolAddress((void**)&ga, g_attn);

    cudaFuncSetAttribute(gemm_mma, cudaFuncAttributeMaxDynamicSharedMemorySize, GEMM_SMEM);
    cudaFuncSetAttribute(attn_mma, cudaFuncAttributeMaxDynamicSharedMemorySize, ATTN_SMEM);

    const float scaling = 0.125f;  // Dd^-0.5

    dim3 gThreads(256);
    dim3 gGridProj(Ee / BN, Mtot / BM);     // (6, 64)

    gemm_mma<<<gGridProj, gThreads, GEMM_SMEM>>>(query, Wq, bq, gq, Mtot, Ee, Ee, scaling);
    gemm_mma<<<gGridProj, gThreads, GEMM_SMEM>>>(query, Wk, bk, gk, Mtot, Ee, Ee, 1.0f);
    gemm_mma<<<gGridProj, gThreads, GEMM_SMEM>>>(query, Wv, bv, gv, Mtot, Ee, Ee, 1.0f);

    dim3 aGrid(Nn / 128, Hh, Bb);           // (8, 12, 8)
    attn_mma<<<aGrid, gThreads, ATTN_SMEM>>>(abias);

    gemm_mma<<<gGridProj, gThreads, GEMM_SMEM>>>(ga, Wo, bo, out, Mtot, Ee, Ee, 1.0f);
}